// round 2
// baseline (speedup 1.0000x reference)
#include <cuda_runtime.h>
#include <cuda_bf16.h>
#include <cstdint>

// ============================================================================
// BinaryConv2D: x(64,56,56,128) NHWC conv w(3,3,128,256) HWIO, SAME, stride 1
// binarize both -> implicit GEMM on legacy mma.sync bf16 (exact in fp32 acc).
// (tcgen05/TMEM path is NOT available: harness ptxas target is base sm_103,
//  which rejects tcgen05.ld/wait — proven in round 1.)
//   M = 64*56*56 pixels (tile 8h x 16w = 128/CTA)
//   N = 256 outch (tile 128/CTA)
//   K = 9 taps * 128 ch, per-tap cp.async double-buffered stage
// ============================================================================

constexpr int X_ELEMS = 64 * 56 * 56 * 128;   // 25,690,112
constexpr int W_ELEMS = 9 * 256 * 128;        // 294,912

__device__ __nv_bfloat16 g_xb[X_ELEMS];       // binarized x, NHWC bf16
__device__ __nv_bfloat16 g_wb[W_ELEMS];       // binarized w, [tap][o][c]

// ---------------------------------------------------------------------------
// preprocessing
// ---------------------------------------------------------------------------
__global__ void bin_x_kernel(const float* __restrict__ x) {
    int t = blockIdx.x * blockDim.x + threadIdx.x;
    int base = t * 4;
    if (base >= X_ELEMS) return;
    float4 v = *reinterpret_cast<const float4*>(x + base);
    uint32_t w0 = (v.x >= 0.0f ? 0x3F80u : 0xBF80u) |
                  ((v.y >= 0.0f ? 0x3F80u : 0xBF80u) << 16);
    uint32_t w1 = (v.z >= 0.0f ? 0x3F80u : 0xBF80u) |
                  ((v.w >= 0.0f ? 0x3F80u : 0xBF80u) << 16);
    *reinterpret_cast<uint2*>(g_xb + base) = make_uint2(w0, w1);
}

__global__ void bin_w_kernel(const float* __restrict__ w) {
    int t = blockIdx.x * blockDim.x + threadIdx.x;
    if (t >= W_ELEMS) return;
    int c   = t & 127;
    int o   = (t >> 7) & 255;
    int tap = t >> 15;
    float v = w[(tap * 128 + c) * 256 + o];      // HWIO source
    reinterpret_cast<unsigned short*>(g_wb)[t] = (v >= 0.0f) ? 0x3F80 : 0xBF80;
}

// ---------------------------------------------------------------------------
// PTX helpers
// ---------------------------------------------------------------------------
static __device__ __forceinline__ void ldmatrix_x4(uint32_t& r0, uint32_t& r1,
                                                   uint32_t& r2, uint32_t& r3,
                                                   uint32_t addr) {
    asm volatile("ldmatrix.sync.aligned.m8n8.x4.shared.b16 {%0,%1,%2,%3}, [%4];"
                 : "=r"(r0), "=r"(r1), "=r"(r2), "=r"(r3) : "r"(addr));
}

static __device__ __forceinline__ void mma16816(float* c, const uint32_t* a,
                                                const uint32_t* b) {
    asm volatile(
        "mma.sync.aligned.m16n8k16.row.col.f32.bf16.bf16.f32 "
        "{%0,%1,%2,%3}, {%4,%5,%6,%7}, {%8,%9}, {%0,%1,%2,%3};"
        : "+f"(c[0]), "+f"(c[1]), "+f"(c[2]), "+f"(c[3])
        : "r"(a[0]), "r"(a[1]), "r"(a[2]), "r"(a[3]), "r"(b[0]), "r"(b[1]));
}

static __device__ __forceinline__ void cp16(uint32_t dst, const void* src, int srcsize) {
    asm volatile("cp.async.cg.shared.global [%0], [%1], 16, %2;"
                 :: "r"(dst), "l"(src), "r"(srcsize) : "memory");
}

// swizzled smem byte offset within a 128x256B tile: row*256 + (chunk^(row&15))*16
static __device__ __forceinline__ uint32_t swz(int row, int chunk) {
    return (uint32_t)((row << 8) + ((chunk ^ (row & 15)) << 4));
}

// ---------------------------------------------------------------------------
// main kernel: 256 threads, 8 warps (4 M x 2 N), warp tile 32x64
// ---------------------------------------------------------------------------
constexpr int STAGE = 65536;                 // A 32KB + B 32KB
constexpr int SMEM_TOTAL = 2 * STAGE;

__global__ void __launch_bounds__(256, 1)
conv_hmma_kernel(float* __restrict__ out) {
    extern __shared__ char smem[];
    uint32_t sbase = (uint32_t)__cvta_generic_to_shared(smem);

    int tid  = threadIdx.x;
    int lane = tid & 31;
    int wid  = tid >> 5;
    int warp_m = wid >> 1;       // 0..3 -> 32 rows each
    int warp_n = wid & 1;        // 0..1 -> 64 cols each

    // tile decode: blockIdx = ((img*28 + ht*4 + wt) << 1) | ntile
    int b = blockIdx.x;
    int ntile = b & 1;
    int mt = b >> 1;
    int img = mt / 28;
    int rr  = mt - img * 28;
    int h0 = (rr >> 2) * 8;
    int w0 = (rr & 3) * 16;
    int n0 = ntile * 128;

    // per-thread load assignment: row = tid>>1 (0..127), 8 chunks of 16B
    int lrow  = tid >> 1;
    int lch0  = (tid & 1) * 8;
    int li    = lrow >> 4;       // pixel h offset in tile
    int lj    = lrow & 15;       // pixel w offset in tile

    float acc[2][8][4];
    #pragma unroll
    for (int mi = 0; mi < 2; ++mi)
        #pragma unroll
        for (int ni = 0; ni < 8; ++ni)
            #pragma unroll
            for (int q = 0; q < 4; ++q) acc[mi][ni][q] = 0.0f;

    // ---- issue loads for one tap into stage s ----
    auto issue = [&](int tap, int s) {
        int kh = tap / 3, kw = tap - kh * 3;
        int hh = h0 + li + kh - 1;
        int ww = w0 + lj + kw - 1;
        bool valid = ((unsigned)hh < 56u) && ((unsigned)ww < 56u);
        const char* srcA = valid
            ? (const char*)(g_xb + (((img * 56 + hh) * 56 + ww) << 7))
            : (const char*)g_xb;
        int asz = valid ? 16 : 0;
        uint32_t dA = sbase + s * STAGE;
        uint32_t dB = dA + 32768;
        const char* srcB = (const char*)(g_wb + (((tap * 256) + n0 + lrow) << 7));
        #pragma unroll
        for (int q = 0; q < 8; ++q) {
            int ch = lch0 + q;
            cp16(dA + swz(lrow, ch), srcA + ch * 16, asz);
            cp16(dB + swz(lrow, ch), srcB + ch * 16, 16);
        }
        asm volatile("cp.async.commit_group;" ::: "memory");
    };

    // ---- compute one tap from stage s ----
    auto compute = [&](int s) {
        uint32_t sA = sbase + s * STAGE;
        uint32_t sB = sA + 32768;
        #pragma unroll
        for (int k = 0; k < 8; ++k) {
            int chunk = 2 * k + (lane >> 4);
            uint32_t a[2][4];
            #pragma unroll
            for (int mi = 0; mi < 2; ++mi) {
                int row = warp_m * 32 + mi * 16 + (lane & 15);
                ldmatrix_x4(a[mi][0], a[mi][1], a[mi][2], a[mi][3],
                            sA + swz(row, chunk));
            }
            uint32_t bf[8][2];
            #pragma unroll
            for (int bi = 0; bi < 4; ++bi) {
                int row = warp_n * 64 + bi * 16 + (lane & 15);
                uint32_t r0, r1, r2, r3;
                ldmatrix_x4(r0, r1, r2, r3, sB + swz(row, chunk));
                bf[2 * bi][0] = r0; bf[2 * bi][1] = r2;
                bf[2 * bi + 1][0] = r1; bf[2 * bi + 1][1] = r3;
            }
            #pragma unroll
            for (int mi = 0; mi < 2; ++mi)
                #pragma unroll
                for (int ni = 0; ni < 8; ++ni)
                    mma16816(acc[mi][ni], a[mi], bf[ni]);
        }
    };

    // ---- 2-stage pipeline over 9 taps ----
    issue(0, 0);
    for (int tap = 0; tap < 9; ++tap) {
        if (tap < 8) {
            issue(tap + 1, (tap + 1) & 1);
            asm volatile("cp.async.wait_group 1;" ::: "memory");
        } else {
            asm volatile("cp.async.wait_group 0;" ::: "memory");
        }
        __syncthreads();
        compute(tap & 1);
        __syncthreads();
    }

    // ---- epilogue: direct STG.64 of fp32 accumulators ----
    int colbase = n0 + warp_n * 64 + (lane & 3) * 2;
    #pragma unroll
    for (int mi = 0; mi < 2; ++mi) {
        #pragma unroll
        for (int half = 0; half < 2; ++half) {
            int p = warp_m * 32 + mi * 16 + half * 8 + (lane >> 2);
            int j = p & 15;
            int ww = w0 + j;
            if (ww >= 56) continue;
            int hh = h0 + (p >> 4);
            float* op = out + (((img * 56 + hh) * 56 + ww) << 8);
            #pragma unroll
            for (int ni = 0; ni < 8; ++ni) {
                float2 v;
                v.x = acc[mi][ni][half * 2 + 0];
                v.y = acc[mi][ni][half * 2 + 1];
                *reinterpret_cast<float2*>(op + colbase + ni * 8) = v;
            }
        }
    }
}

// ---------------------------------------------------------------------------
// launch
// ---------------------------------------------------------------------------
extern "C" void kernel_launch(void* const* d_in, const int* in_sizes, int n_in,
                              void* d_out, int out_size) {
    const float* x = (const float*)d_in[0];
    const float* w = (const float*)d_in[1];
    float* out = (float*)d_out;

    bin_x_kernel<<<(X_ELEMS / 4 + 255) / 256, 256>>>(x);
    bin_w_kernel<<<(W_ELEMS + 255) / 256, 256>>>(w);

    cudaFuncSetAttribute(conv_hmma_kernel,
                         cudaFuncAttributeMaxDynamicSharedMemorySize, SMEM_TOTAL);
    // 64 images * 7 h-tiles * 4 w-tiles * 2 n-tiles = 3584 CTAs
    conv_hmma_kernel<<<3584, 256, SMEM_TOTAL>>>(out);
}

// round 3
// speedup vs baseline: 1.5240x; 1.5240x over previous
#include <cuda_runtime.h>
#include <cstdint>

// ============================================================================
// BinaryConv2D: x(64,56,56,128) NHWC conv w(3,3,128,256) HWIO, SAME, stride 1.
// binarize both -> implicit GEMM on mma.sync m16n8k32 e4m3 (exact: products
// are ±1 in e4m3, sums <= 1152 in fp32).
// CTA: 128 pixels (8h x 16w) x 128 outch. 4 warps, warp tile 64x64.
// SMEM-resident: A halo (10x18 px, 23KB, loaded once) + B all 9 taps (144KB).
// Mainloop has ZERO __syncthreads and zero gmem traffic.
// (tcgen05/TMEM unavailable: harness ptxas targets base sm_103 — proven R1.)
// ============================================================================

constexpr int X_ELEMS = 64 * 56 * 56 * 128;   // 25,690,112
constexpr int W_ELEMS = 9 * 256 * 128;        // 294,912

__device__ uint8_t g_xq[X_ELEMS];             // binarized x, NHWC e4m3
__device__ uint8_t g_wq[W_ELEMS];             // binarized w, [tap][o][c] e4m3

// ---------------------------------------------------------------------------
// preprocessing: e4m3 +1.0 = 0x38, -1.0 = 0xB8
// ---------------------------------------------------------------------------
__global__ void bin_x_kernel(const float* __restrict__ x) {
    int t = blockIdx.x * blockDim.x + threadIdx.x;
    int base = t * 8;
    if (base >= X_ELEMS) return;
    const float4* p = reinterpret_cast<const float4*>(x + base);
    float4 v0 = p[0], v1 = p[1];
    uint32_t lo = (v0.x >= 0.0f ? 0x38u : 0xB8u)        |
                  ((v0.y >= 0.0f ? 0x38u : 0xB8u) << 8)  |
                  ((v0.z >= 0.0f ? 0x38u : 0xB8u) << 16) |
                  ((v0.w >= 0.0f ? 0x38u : 0xB8u) << 24);
    uint32_t hi = (v1.x >= 0.0f ? 0x38u : 0xB8u)        |
                  ((v1.y >= 0.0f ? 0x38u : 0xB8u) << 8)  |
                  ((v1.z >= 0.0f ? 0x38u : 0xB8u) << 16) |
                  ((v1.w >= 0.0f ? 0x38u : 0xB8u) << 24);
    *reinterpret_cast<uint2*>(g_xq + base) = make_uint2(lo, hi);
}

__global__ void bin_w_kernel(const float* __restrict__ w) {
    int t = blockIdx.x * blockDim.x + threadIdx.x;
    if (t >= W_ELEMS) return;
    int c   = t & 127;
    int o   = (t >> 7) & 255;
    int tap = t >> 15;
    float v = w[(tap * 128 + c) * 256 + o];   // HWIO source
    g_wq[t] = (v >= 0.0f) ? 0x38 : 0xB8;
}

// ---------------------------------------------------------------------------
// PTX helpers
// ---------------------------------------------------------------------------
static __device__ __forceinline__ void ldmatrix_x4(uint32_t& r0, uint32_t& r1,
                                                   uint32_t& r2, uint32_t& r3,
                                                   uint32_t addr) {
    asm volatile("ldmatrix.sync.aligned.m8n8.x4.shared.b16 {%0,%1,%2,%3}, [%4];"
                 : "=r"(r0), "=r"(r1), "=r"(r2), "=r"(r3) : "r"(addr));
}

static __device__ __forceinline__ void mma_fp8(float* c, const uint32_t* a,
                                               const uint32_t* b) {
    asm volatile(
        "mma.sync.aligned.m16n8k32.row.col.f32.e4m3.e4m3.f32 "
        "{%0,%1,%2,%3}, {%4,%5,%6,%7}, {%8,%9}, {%0,%1,%2,%3};"
        : "+f"(c[0]), "+f"(c[1]), "+f"(c[2]), "+f"(c[3])
        : "r"(a[0]), "r"(a[1]), "r"(a[2]), "r"(a[3]), "r"(b[0]), "r"(b[1]));
}

static __device__ __forceinline__ void cp16(uint32_t dst, const void* src, int srcsize) {
    asm volatile("cp.async.cg.shared.global [%0], [%1], 16, %2;"
                 :: "r"(dst), "l"(src), "r"(srcsize) : "memory");
}

// ---------------------------------------------------------------------------
// main kernel: 128 threads, 4 warps (2M x 2N), warp tile 64x64
// SMEM: A halo 180 rows x 128B = 23040, B 1152 rows x 128B = 147456
// row layout: 8 chunks of 16B, swizzle chunk ^= (row & 7)
// ---------------------------------------------------------------------------
constexpr int SMEM_A = 0;
constexpr int SMEM_B = 23040;
constexpr int SMEM_TOTAL = 23040 + 147456;   // 170,496 B

__global__ void __launch_bounds__(128, 1)
conv_fp8_kernel(float* __restrict__ out) {
    extern __shared__ char smem[];
    uint32_t sbase = (uint32_t)__cvta_generic_to_shared(smem);

    int tid  = threadIdx.x;
    int lane = tid & 31;
    int wid  = tid >> 5;
    int warp_m = wid >> 1;       // 0..1 -> 64 pixel rows each
    int warp_n = wid & 1;        // 0..1 -> 64 outch each

    // tile decode: blockIdx = ((img*28 + ht*4 + wt) << 1) | ntile
    int b = blockIdx.x;
    int ntile = b & 1;
    int mt = b >> 1;
    int img = mt / 28;
    int rr  = mt - img * 28;
    int h0 = (rr >> 2) * 8;
    int w0 = (rr & 3) * 16;
    int n0 = ntile * 128;

    // ---- stage A halo (10h x 18w pixels, zero-filled outside image) ----
    for (int idx = tid; idx < 1440; idx += 128) {        // 180 rows x 8 chunks
        int row = idx >> 3, ch = idx & 7;
        int hr = row / 18;
        int wc = row - hr * 18;
        int hh = h0 + hr - 1;
        int ww = w0 + wc - 1;
        bool v = ((unsigned)hh < 56u) && ((unsigned)ww < 56u);
        const char* src = v ? (const char*)(g_xq + (((img * 56 + hh) * 56 + ww) << 7))
                            : (const char*)g_xq;
        cp16(sbase + SMEM_A + (row << 7) + ((ch ^ (row & 7)) << 4),
             src + ch * 16, v ? 16 : 0);
    }
    // ---- stage B: all 9 taps x 128 outch (this CTA's n-half) ----
    for (int idx = tid; idx < 9216; idx += 128) {        // 1152 rows x 8 chunks
        int row = idx >> 3, ch = idx & 7;
        int tap = row >> 7;
        int ol  = row & 127;
        const char* src = (const char*)(g_wq + ((tap * 256 + n0 + ol) << 7));
        cp16(sbase + SMEM_B + (row << 7) + ((ch ^ (row & 7)) << 4),
             src + ch * 16, 16);
    }
    asm volatile("cp.async.commit_group;" ::: "memory");
    asm volatile("cp.async.wait_group 0;" ::: "memory");
    __syncthreads();

    // ---- per-lane fragment row bases ----
    int lane15 = lane & 15;
    int lanehi = lane >> 4;
    int rbase[4];
    #pragma unroll
    for (int mi = 0; mi < 4; ++mi) {
        int p = warp_m * 64 + mi * 16 + lane15;          // pixel index 0..127
        rbase[mi] = (p >> 4) * 18 + (p & 15);            // halo row at tap (0,0)
    }
    int brow0 = warp_n * 64 + lane15;

    float acc[4][8][4];
    #pragma unroll
    for (int mi = 0; mi < 4; ++mi)
        #pragma unroll
        for (int ni = 0; ni < 8; ++ni)
            #pragma unroll
            for (int q = 0; q < 4; ++q) acc[mi][ni][q] = 0.0f;

    // ---- mainloop: 9 taps x 4 k-steps, all from resident SMEM, no syncs ----
    int tapoff = 0;   // kh*18 + kw
    int kw = 0;
    for (int tap = 0; tap < 9; ++tap) {
        int btap = tap << 7;
        #pragma unroll
        for (int k = 0; k < 4; ++k) {
            int chunk = 2 * k + lanehi;
            uint32_t a[4][4];
            #pragma unroll
            for (int mi = 0; mi < 4; ++mi) {
                int hrow = rbase[mi] + tapoff;
                ldmatrix_x4(a[mi][0], a[mi][1], a[mi][2], a[mi][3],
                            sbase + SMEM_A + (hrow << 7) + ((chunk ^ (hrow & 7)) << 4));
            }
            uint32_t bf[8][2];
            #pragma unroll
            for (int bi = 0; bi < 4; ++bi) {
                int br = btap + brow0 + bi * 16;
                uint32_t r0, r1, r2, r3;
                ldmatrix_x4(r0, r1, r2, r3,
                            sbase + SMEM_B + (br << 7) + ((chunk ^ (br & 7)) << 4));
                bf[2 * bi][0] = r0; bf[2 * bi][1] = r2;
                bf[2 * bi + 1][0] = r1; bf[2 * bi + 1][1] = r3;
            }
            #pragma unroll
            for (int mi = 0; mi < 4; ++mi)
                #pragma unroll
                for (int ni = 0; ni < 8; ++ni)
                    mma_fp8(acc[mi][ni], a[mi], bf[ni]);
        }
        // advance tap offset: kw 0->1->2->wrap (kh++)
        if (kw == 2) { kw = 0; tapoff += 16; }           // +18 - 2
        else         { kw++;   tapoff += 1;  }
    }

    // ---- epilogue: direct fp32 stores ----
    int colbase = n0 + warp_n * 64 + (lane & 3) * 2;
    #pragma unroll
    for (int mi = 0; mi < 4; ++mi) {
        #pragma unroll
        for (int half = 0; half < 2; ++half) {
            int p = warp_m * 64 + mi * 16 + half * 8 + (lane >> 2);
            int j = p & 15;
            int ww = w0 + j;
            if (ww >= 56) continue;
            int hh = h0 + (p >> 4);
            float* op = out + (((img * 56 + hh) * 56 + ww) << 8);
            #pragma unroll
            for (int ni = 0; ni < 8; ++ni) {
                float2 v;
                v.x = acc[mi][ni][half * 2 + 0];
                v.y = acc[mi][ni][half * 2 + 1];
                *reinterpret_cast<float2*>(op + colbase + ni * 8) = v;
            }
        }
    }
}

// ---------------------------------------------------------------------------
// launch
// ---------------------------------------------------------------------------
extern "C" void kernel_launch(void* const* d_in, const int* in_sizes, int n_in,
                              void* d_out, int out_size) {
    const float* x = (const float*)d_in[0];
    const float* w = (const float*)d_in[1];
    float* out = (float*)d_out;

    bin_x_kernel<<<(X_ELEMS / 8 + 255) / 256, 256>>>(x);
    bin_w_kernel<<<(W_ELEMS + 255) / 256, 256>>>(w);

    cudaFuncSetAttribute(conv_fp8_kernel,
                         cudaFuncAttributeMaxDynamicSharedMemorySize, SMEM_TOTAL);
    // 64 images * 7 h-tiles * 4 w-tiles * 2 n-tiles = 3584 CTAs
    conv_fp8_kernel<<<3584, 128, SMEM_TOTAL>>>(out);
}

// round 4
// speedup vs baseline: 2.0331x; 1.3340x over previous
#include <cuda_runtime.h>
#include <cstdint>

// ============================================================================
// BinaryConv2D: x(64,56,56,128) NHWC conv w(3,3,128,256) HWIO, SAME, stride 1.
// binarize both -> implicit GEMM on mma.sync m16n8k32 e4m3 (exact: products
// ±1 in e4m3, sums <= 1152 in fp32).
// CTA: 128 pixels (8h x 16w) x 128 outch. 256 threads, 8 warps (4M x 2N),
// warp tile 32 x 64. 2 CTAs/SM (23KB smem, <=128 regs).
//   A: SMEM-resident 10x18 halo, loaded once, read via ldmatrix. No syncs in
//      mainloop.
//   B: NO smem. Weights precomputed in mma-fragment order; each thread LDG.64s
//      its {b0,b1} fragment straight to registers (L2/L1-hot, 288KB total).
// (tcgen05/TMEM unavailable: harness ptxas targets base sm_103 — proven R1.)
// ============================================================================

constexpr int X_ELEMS = 64 * 56 * 56 * 128;   // 25,690,112
constexpr int WF_U2   = 9 * 4 * 32 * 32;      // 36,864 uint2 = 294,912 B

__device__ uint8_t g_xq[X_ELEMS];             // binarized x, NHWC e4m3
__device__ uint2   g_wf[WF_U2];               // weights, fragment-ordered

// ---------------------------------------------------------------------------
// preprocessing: e4m3 +1.0 = 0x38, -1.0 = 0xB8
// ---------------------------------------------------------------------------
__global__ void bin_x_kernel(const float* __restrict__ x) {
    int t = blockIdx.x * blockDim.x + threadIdx.x;
    int base = t * 8;
    if (base >= X_ELEMS) return;
    const float4* p = reinterpret_cast<const float4*>(x + base);
    float4 v0 = p[0], v1 = p[1];
    uint32_t lo = (v0.x >= 0.0f ? 0x38u : 0xB8u)        |
                  ((v0.y >= 0.0f ? 0x38u : 0xB8u) << 8)  |
                  ((v0.z >= 0.0f ? 0x38u : 0xB8u) << 16) |
                  ((v0.w >= 0.0f ? 0x38u : 0xB8u) << 24);
    uint32_t hi = (v1.x >= 0.0f ? 0x38u : 0xB8u)        |
                  ((v1.y >= 0.0f ? 0x38u : 0xB8u) << 8)  |
                  ((v1.z >= 0.0f ? 0x38u : 0xB8u) << 16) |
                  ((v1.w >= 0.0f ? 0x38u : 0xB8u) << 24);
    *reinterpret_cast<uint2*>(g_xq + base) = make_uint2(lo, hi);
}

// fragment order: u = ((tap*4 + k)*32 + g)*32 + lane
//   outch o = g*8 + (lane>>2)
//   reg x bytes b: ch = k*32 + (lane&3)*4 + b        (m16n8k32 .col B frag)
//   reg y bytes b: ch = k*32 + 16 + (lane&3)*4 + b
__global__ void bin_w_kernel(const float* __restrict__ w) {
    int u = blockIdx.x * blockDim.x + threadIdx.x;
    if (u >= WF_U2) return;
    int lane = u & 31;
    int g    = (u >> 5) & 31;
    int k    = (u >> 10) & 3;
    int tap  = u >> 12;
    int o  = g * 8 + (lane >> 2);
    int cb = k * 32 + (lane & 3) * 4;
    uint32_t r0 = 0, r1 = 0;
    #pragma unroll
    for (int b = 0; b < 4; ++b) {
        float v0 = w[(tap * 128 + cb + b) * 256 + o];        // HWIO
        float v1 = w[(tap * 128 + cb + 16 + b) * 256 + o];
        r0 |= (v0 >= 0.0f ? 0x38u : 0xB8u) << (8 * b);
        r1 |= (v1 >= 0.0f ? 0x38u : 0xB8u) << (8 * b);
    }
    g_wf[u] = make_uint2(r0, r1);
}

// ---------------------------------------------------------------------------
// PTX helpers
// ---------------------------------------------------------------------------
static __device__ __forceinline__ void ldmatrix_x4(uint32_t& r0, uint32_t& r1,
                                                   uint32_t& r2, uint32_t& r3,
                                                   uint32_t addr) {
    asm volatile("ldmatrix.sync.aligned.m8n8.x4.shared.b16 {%0,%1,%2,%3}, [%4];"
                 : "=r"(r0), "=r"(r1), "=r"(r2), "=r"(r3) : "r"(addr));
}

static __device__ __forceinline__ void mma_fp8(float* c, const uint32_t* a,
                                               uint32_t b0, uint32_t b1) {
    asm volatile(
        "mma.sync.aligned.m16n8k32.row.col.f32.e4m3.e4m3.f32 "
        "{%0,%1,%2,%3}, {%4,%5,%6,%7}, {%8,%9}, {%0,%1,%2,%3};"
        : "+f"(c[0]), "+f"(c[1]), "+f"(c[2]), "+f"(c[3])
        : "r"(a[0]), "r"(a[1]), "r"(a[2]), "r"(a[3]), "r"(b0), "r"(b1));
}

static __device__ __forceinline__ void cp16(uint32_t dst, const void* src, int srcsize) {
    asm volatile("cp.async.cg.shared.global [%0], [%1], 16, %2;"
                 :: "r"(dst), "l"(src), "r"(srcsize) : "memory");
}

// ---------------------------------------------------------------------------
// main kernel: 256 threads, 8 warps (4M x 2N), warp tile 32x64
// SMEM: A halo only, 180 rows x 128B = 23040 B (swizzle: chunk ^= row&7)
// ---------------------------------------------------------------------------
constexpr int SMEM_TOTAL = 23040;

__global__ void __launch_bounds__(256, 2)
conv_fp8_kernel(float* __restrict__ out) {
    extern __shared__ char smem[];
    uint32_t sbase = (uint32_t)__cvta_generic_to_shared(smem);

    int tid  = threadIdx.x;
    int lane = tid & 31;
    int wid  = tid >> 5;
    int warp_m = wid >> 1;       // 0..3 -> 32 pixel rows each
    int warp_n = wid & 1;        // 0..1 -> 64 outch each

    // tile decode: blockIdx = ((img*28 + ht*4 + wt) << 1) | ntile
    int b = blockIdx.x;
    int ntile = b & 1;
    int mt = b >> 1;
    int img = mt / 28;
    int rr  = mt - img * 28;
    int h0 = (rr >> 2) * 8;
    int w0 = (rr & 3) * 16;
    int n0 = ntile * 128;

    // ---- stage A halo (10h x 18w pixels, zero-filled outside image) ----
    for (int idx = tid; idx < 1440; idx += 256) {        // 180 rows x 8 chunks
        int row = idx >> 3, ch = idx & 7;
        int hr = row / 18;
        int wc = row - hr * 18;
        int hh = h0 + hr - 1;
        int ww = w0 + wc - 1;
        bool v = ((unsigned)hh < 56u) && ((unsigned)ww < 56u);
        const char* src = v ? (const char*)(g_xq + (((img * 56 + hh) * 56 + ww) << 7))
                            : (const char*)g_xq;
        cp16(sbase + (row << 7) + ((ch ^ (row & 7)) << 4), src + ch * 16, v ? 16 : 0);
    }
    asm volatile("cp.async.commit_group;" ::: "memory");
    asm volatile("cp.async.wait_group 0;" ::: "memory");
    __syncthreads();

    // ---- per-lane fragment row bases ----
    int lane15 = lane & 15;
    int lanehi = lane >> 4;
    int rbase[2];
    #pragma unroll
    for (int mi = 0; mi < 2; ++mi) {
        int p = warp_m * 32 + mi * 16 + lane15;          // pixel index 0..127
        rbase[mi] = (p >> 4) * 18 + (p & 15);            // halo row at tap (0,0)
    }
    // B fragment pointer base for this thread: g = ntile*16 + warp_n*8 + ni
    const uint2* wf0 = g_wf + (uint32_t)((ntile * 16 + warp_n * 8) * 32 + lane);

    float acc[2][8][4];
    #pragma unroll
    for (int mi = 0; mi < 2; ++mi)
        #pragma unroll
        for (int ni = 0; ni < 8; ++ni)
            #pragma unroll
            for (int q = 0; q < 4; ++q) acc[mi][ni][q] = 0.0f;

    // ---- mainloop: 9 taps x 4 k-steps, no barriers, no smem writes ----
    int tapoff = 0;   // kh*18 + kw
    int kw = 0;
    for (int tap = 0; tap < 9; ++tap) {
        const uint2* wft = wf0 + (uint32_t)(tap * 4 * 32 * 32);
        #pragma unroll
        for (int k = 0; k < 4; ++k) {
            int chunk = 2 * k + lanehi;
            uint32_t a[2][4];
            #pragma unroll
            for (int mi = 0; mi < 2; ++mi) {
                int hrow = rbase[mi] + tapoff;
                ldmatrix_x4(a[mi][0], a[mi][1], a[mi][2], a[mi][3],
                            sbase + (hrow << 7) + ((chunk ^ (hrow & 7)) << 4));
            }
            const uint2* wfk = wft + (uint32_t)(k * 32 * 32);
            #pragma unroll
            for (int ni = 0; ni < 8; ++ni) {
                uint2 bv = __ldg(wfk + ni * 32);
                mma_fp8(acc[0][ni], a[0], bv.x, bv.y);
                mma_fp8(acc[1][ni], a[1], bv.x, bv.y);
            }
        }
        if (kw == 2) { kw = 0; tapoff += 16; }           // +18 - 2
        else         { kw++;   tapoff += 1;  }
    }

    // ---- epilogue: direct fp32 stores ----
    int colbase = n0 + warp_n * 64 + (lane & 3) * 2;
    #pragma unroll
    for (int mi = 0; mi < 2; ++mi) {
        #pragma unroll
        for (int half = 0; half < 2; ++half) {
            int p = warp_m * 32 + mi * 16 + half * 8 + (lane >> 2);
            int j = p & 15;
            int ww = w0 + j;
            if (ww >= 56) continue;
            int hh = h0 + (p >> 4);
            float* op = out + (((img * 56 + hh) * 56 + ww) << 8);
            #pragma unroll
            for (int ni = 0; ni < 8; ++ni) {
                float2 v;
                v.x = acc[mi][ni][half * 2 + 0];
                v.y = acc[mi][ni][half * 2 + 1];
                *reinterpret_cast<float2*>(op + colbase + ni * 8) = v;
            }
        }
    }
}

// ---------------------------------------------------------------------------
// launch
// ---------------------------------------------------------------------------
extern "C" void kernel_launch(void* const* d_in, const int* in_sizes, int n_in,
                              void* d_out, int out_size) {
    const float* x = (const float*)d_in[0];
    const float* w = (const float*)d_in[1];
    float* out = (float*)d_out;

    bin_x_kernel<<<(X_ELEMS / 8 + 255) / 256, 256>>>(x);
    bin_w_kernel<<<(WF_U2 + 255) / 256, 256>>>(w);

    cudaFuncSetAttribute(conv_fp8_kernel,
                         cudaFuncAttributeMaxDynamicSharedMemorySize, SMEM_TOTAL);
    // 64 images * 7 h-tiles * 4 w-tiles * 2 n-tiles = 3584 CTAs
    conv_fp8_kernel<<<3584, 256, SMEM_TOTAL>>>(out);
}